// round 2
// baseline (speedup 1.0000x reference)
#include <cuda_runtime.h>
#include <cstdint>

// Problem shapes (fixed by the dataset)
#define B   8
#define NBOX 32
#define C   80
#define NCH (B * C)   // 640

// Per-(batch,channel) accumulators (scratch via __device__ globals — no allocs)
__device__ float g_nl[NCH];   // sum of neg_loss terms
__device__ float g_pl[NCH];   // sum of pos_loss terms
__device__ int   g_np[NCH];   // num_pos

// ---------------------------------------------------------------------------
// log(1-p) * p^2 with p = clip(sigmoid(h), 1e-4, 1-1e-4)
__device__ __forceinline__ float neg_term(float h) {
    float e = __expf(-h);
    float p = __fdividef(1.0f, 1.0f + e);
    p = fminf(fmaxf(p, 1e-4f), 1.0f - 1e-4f);
    return __logf(1.0f - p) * p * p;
}

// Box -> (center x, center y, radius, 1/(2 sigma^2)) at a given square level W.
// __noinline__ : exactly one compiled instance so the "self" and "conflict"
// evaluations of the SAME box produce bitwise-identical parameters (needed for
// the deterministic argmax dedup below).
__device__ __noinline__ void box_params(float4 bx, int W,
                                        int& x, int& y, int& r, float& inv2s2) {
    x = (int)floorf(bx.x * (float)W);
    y = (int)floorf(bx.y * (float)W);
    float bw = bx.z * (float)W;
    float bh = bx.w * (float)W;
    int rr = (int)floorf((bw + bh) * 0.25f);
    r = rr < 1 ? 1 : rr;
    float sigma = (float)(2 * r + 1) / 6.0f;
    inv2s2 = 1.0f / (2.0f * sigma * sigma);
}

// ---------------------------------------------------------------------------
__global__ void zero_kernel() {
    int i = blockIdx.x * blockDim.x + threadIdx.x;
    if (i < NCH) { g_nl[i] = 0.0f; g_pl[i] = 0.0f; g_np[i] = 0; }
}

// Baseline: neg_loss with target==0 for every pixel, reduced per (b,c) channel.
// grid = (640 channels, 3 levels), block = 256. float4 loads for bandwidth.
__global__ void baseline_kernel(const float* __restrict__ h0,
                                const float* __restrict__ h1,
                                const float* __restrict__ h2) {
    int ch  = blockIdx.x;
    int lvl = blockIdx.y;
    const float* base; int HW;
    if      (lvl == 0) { base = h0; HW = 128 * 128; }
    else if (lvl == 1) { base = h1; HW = 64 * 64; }
    else               { base = h2; HW = 32 * 32; }

    const float4* p4 = reinterpret_cast<const float4*>(base + (size_t)ch * HW);
    int n4 = HW >> 2;
    float acc = 0.0f;
    for (int i = threadIdx.x; i < n4; i += blockDim.x) {
        float4 v = p4[i];
        acc += neg_term(v.x);
        acc += neg_term(v.y);
        acc += neg_term(v.z);
        acc += neg_term(v.w);
    }
    __shared__ float sm[256];
    sm[threadIdx.x] = acc;
    __syncthreads();
    for (int s = 128; s > 0; s >>= 1) {
        if (threadIdx.x < s) sm[threadIdx.x] += sm[threadIdx.x + s];
        __syncthreads();
    }
    if (threadIdx.x == 0) atomicAdd(&g_nl[ch], sm[0]);
}

// Corrections: one block per (box, level). Walks the Gaussian window, computes
// the true target t = max over same-class boxes (dedup: pixel is processed by
// the LOWEST-index box achieving the max), and adds the delta vs baseline.
__global__ void corr_kernel(const float* __restrict__ h0,
                            const float* __restrict__ h1,
                            const float* __restrict__ h2,
                            const float* __restrict__ boxes,
                            const int*   __restrict__ labels) {
    int boxId = blockIdx.x;          // 0..B*NBOX-1
    int lvl   = blockIdx.y;
    int b = boxId >> 5, n = boxId & 31;
    int W = (lvl == 0) ? 128 : ((lvl == 1) ? 64 : 32);
    const float* heat = (lvl == 0) ? h0 : ((lvl == 1) ? h1 : h2);

    int c  = labels[b * NBOX + n];
    int bc = b * C + c;

    float4 bx = reinterpret_cast<const float4*>(boxes)[b * NBOX + n];
    int xi, yi, ri; float invi;
    box_params(bx, W, xi, yi, ri, invi);

    // Conflicting boxes (same batch, same label), parameters in smem.
    __shared__ int   sx[NBOX], sy[NBOX], sr[NBOX], sjj[NBOX];
    __shared__ float sinv[NBOX];
    __shared__ int   scnt;
    if (threadIdx.x == 0) {
        int cnt = 0;
        for (int j = 0; j < NBOX; j++) {
            if (j == n) continue;
            if (labels[b * NBOX + j] == c) {
                float4 bj = reinterpret_cast<const float4*>(boxes)[b * NBOX + j];
                int xj, yj, rj; float invj;
                box_params(bj, W, xj, yj, rj, invj);
                sx[cnt] = xj; sy[cnt] = yj; sr[cnt] = rj;
                sinv[cnt] = invj; sjj[cnt] = j;
                cnt++;
            }
        }
        scnt = cnt;
    }
    __syncthreads();
    int cnt = scnt;

    int x0 = max(xi - ri, 0), x1 = min(xi + ri, W - 1);
    int y0 = max(yi - ri, 0), y1 = min(yi + ri, W - 1);
    int nx = x1 - x0 + 1, ny = y1 - y0 + 1;
    int tot = nx * ny;

    float dnl = 0.0f, dpl = 0.0f;
    int dnp = 0;
    const float* hch = heat + (size_t)bc * W * W;

    for (int k = threadIdx.x; k < tot; k += blockDim.x) {
        int px = x0 + (k % nx);
        int py = y0 + (k / nx);
        int dx = px - xi, dy = py - yi;
        float gi = __expf(-(float)(dx * dx + dy * dy) * invi);
        float best = gi;
        int   owner = n;
        for (int q = 0; q < cnt; q++) {
            int ddx = px - sx[q], ddy = py - sy[q];
            if (abs(ddx) <= sr[q] && abs(ddy) <= sr[q]) {
                float gj = __expf(-(float)(ddx * ddx + ddy * ddy) * sinv[q]);
                if (gj > best || (gj == best && sjj[q] < owner)) {
                    best = gj; owner = sjj[q];
                }
            }
        }
        if (owner != n) continue;   // another (lower-index or larger) box owns this pixel

        float h = hch[py * W + px];
        float e = __expf(-h);
        float p = __fdividef(1.0f, 1.0f + e);
        p = fminf(fmaxf(p, 1e-4f), 1.0f - 1e-4f);
        float lb = __logf(1.0f - p) * p * p;   // baseline neg term at this pixel

        if (best == 1.0f) {
            // pos pixel: remove baseline neg term, add pos term
            dnl -= lb;
            float om = 1.0f - p;
            dpl += __logf(p) * om * om;
            dnp += 1;
        } else {
            // neg pixel with target t: weight (1-t)^4 instead of 1
            float u = 1.0f - best;
            float w = (u * u) * (u * u);
            dnl += lb * (w - 1.0f);
        }
    }

    __shared__ float s1[256], s2[256];
    __shared__ int   s3[256];
    s1[threadIdx.x] = dnl; s2[threadIdx.x] = dpl; s3[threadIdx.x] = dnp;
    __syncthreads();
    for (int s = 128; s > 0; s >>= 1) {
        if (threadIdx.x < s) {
            s1[threadIdx.x] += s1[threadIdx.x + s];
            s2[threadIdx.x] += s2[threadIdx.x + s];
            s3[threadIdx.x] += s3[threadIdx.x + s];
        }
        __syncthreads();
    }
    if (threadIdx.x == 0) {
        if (s1[0] != 0.0f) atomicAdd(&g_nl[bc], s1[0]);
        if (s2[0] != 0.0f) atomicAdd(&g_pl[bc], s2[0]);
        if (s3[0] != 0)    atomicAdd(&g_np[bc], s3[0]);
    }
}

// Finalize: per-channel loss -> mean -> lm/(1+lm)
__global__ void final_kernel(float* __restrict__ out) {
    __shared__ float sm[1024];
    int i = threadIdx.x;
    float loss = 0.0f;
    if (i < NCH) {
        float nl = g_nl[i], pl = g_pl[i];
        int np = g_np[i];
        loss = (np == 0) ? (-nl) : (-(pl + nl) / (float)np);
        loss = fminf(loss, 10.0f);
    }
    sm[i] = loss;
    __syncthreads();
    for (int s = 512; s > 0; s >>= 1) {
        if (i < s) sm[i] += sm[i + s];
        __syncthreads();
    }
    if (i == 0) {
        float mean = sm[0] / (float)NCH;
        float lm = log1pf(mean);
        out[0] = lm / (1.0f + lm);
    }
}

// ---------------------------------------------------------------------------
extern "C" void kernel_launch(void* const* d_in, const int* in_sizes, int n_in,
                              void* d_out, int out_size) {
    const float* h0    = (const float*)d_in[0];
    const float* h1    = (const float*)d_in[1];
    const float* h2    = (const float*)d_in[2];
    const float* boxes = (const float*)d_in[3];
    const int*   labels = (const int*)d_in[4];
    // d_in[5] = image_sizes (int64) — cancels out of the math, unused.
    (void)in_sizes; (void)n_in; (void)out_size;

    zero_kernel<<<(NCH + 255) / 256, 256>>>();
    baseline_kernel<<<dim3(NCH, 3), 256>>>(h0, h1, h2);
    corr_kernel<<<dim3(B * NBOX, 3), 256>>>(h0, h1, h2, boxes, labels);
    final_kernel<<<1, 1024>>>((float*)d_out);
}

// round 3
// speedup vs baseline: 1.0743x; 1.0743x over previous
#include <cuda_runtime.h>
#include <cstdint>

// Problem shapes (fixed by the dataset)
#define B     8
#define NBOX  32
#define C     80
#define NCH   (B * C)        // 640

// Block layout of the single fused kernel:
//   [0,    1280): lvl0 baseline, 2 blocks per channel (2048 float4 each)
//   [1280, 1920): lvl1 baseline, 1 block per channel  (1024 float4)
//   [1920, 2560): lvl2 baseline, 1 block per channel  ( 256 float4)
//   [2560, 3328): corr, (box,lvl) pairs: 256 boxes x 3 levels
#define NB_L0   1280
#define NB_L1   640
#define NB_L2   640
#define NB_CORR (B * NBOX * 3)              // 768
#define TOTAL_BLOCKS (NB_L0 + NB_L1 + NB_L2 + NB_CORR)  // 3328

// Scratch (zero at module load; finalizing block restores zeros every call)
__device__ float    g_nl[NCH];
__device__ float    g_pl[NCH];
__device__ int      g_np[NCH];
__device__ unsigned g_done;

// ---------------------------------------------------------------------------
// log(1-p) * p^2 with p = clip(sigmoid(h), 1e-4, 1-1e-4)
__device__ __forceinline__ float neg_term(float h) {
    float e = __expf(-h);
    float p = __fdividef(1.0f, 1.0f + e);
    p = fminf(fmaxf(p, 1e-4f), 1.0f - 1e-4f);
    return __logf(1.0f - p) * p * p;
}

// Box -> (center, radius, 1/(2 sigma^2)) at square level W. __noinline__ so
// the "self" and "conflict" evaluations of the same box are bitwise identical
// (required by the deterministic argmax dedup).
__device__ __noinline__ void box_params(float4 bx, int W,
                                        int& x, int& y, int& r, float& inv2s2) {
    x = (int)floorf(bx.x * (float)W);
    y = (int)floorf(bx.y * (float)W);
    float bw = bx.z * (float)W;
    float bh = bx.w * (float)W;
    int rr = (int)floorf((bw + bh) * 0.25f);
    r = rr < 1 ? 1 : rr;
    float sigma = (float)(2 * r + 1) / 6.0f;
    inv2s2 = 1.0f / (2.0f * sigma * sigma);
}

__device__ __forceinline__ float warp_sum(float v) {
    #pragma unroll
    for (int o = 16; o > 0; o >>= 1) v += __shfl_xor_sync(0xffffffffu, v, o);
    return v;
}

// ---------------------------------------------------------------------------
__global__ __launch_bounds__(256) void fused_kernel(
    const float* __restrict__ h0, const float* __restrict__ h1,
    const float* __restrict__ h2, const float* __restrict__ boxes,
    const int*   __restrict__ labels, float* __restrict__ out)
{
    const int bid = blockIdx.x;
    const int tid = threadIdx.x;
    const int lane = tid & 31, warp = tid >> 5;

    __shared__ float s_red[8], s_red2[8];
    __shared__ int   s_red3[8];

    if (bid < NB_L0 + NB_L1 + NB_L2) {
        // ---------------- baseline: target==0 neg-loss per channel ----------
        const float* base; int ch, off4, cnt4;
        if (bid < NB_L0)               { ch = bid >> 1;   base = h0; off4 = (bid & 1) * 2048; cnt4 = 2048; }
        else if (bid < NB_L0 + NB_L1)  { ch = bid - NB_L0;        base = h1; off4 = 0; cnt4 = 1024; }
        else                           { ch = bid - NB_L0 - NB_L1; base = h2; off4 = 0; cnt4 = 256;  }
        int chf4 = (base == h0) ? 4096 : ((base == h1) ? 1024 : 256);

        const float4* p4 = reinterpret_cast<const float4*>(base) + (size_t)ch * chf4 + off4;
        float acc = 0.0f;
        for (int i = tid; i < cnt4; i += 256) {
            float4 v = p4[i];
            acc += neg_term(v.x);
            acc += neg_term(v.y);
            acc += neg_term(v.z);
            acc += neg_term(v.w);
        }
        acc = warp_sum(acc);
        if (lane == 0) s_red[warp] = acc;
        __syncthreads();
        if (warp == 0) {
            float s = (lane < 8) ? s_red[lane] : 0.0f;
            s = warp_sum(s);
            if (lane == 0) atomicAdd(&g_nl[ch], s);
        }
    } else {
        // ---------------- corrections: one block per (box, level) ----------
        int t     = bid - (NB_L0 + NB_L1 + NB_L2);
        int lvl   = t >> 8;                       // /256
        int boxId = t & 255;
        int b = boxId >> 5, n = boxId & 31;
        int W = (lvl == 0) ? 128 : ((lvl == 1) ? 64 : 32);
        const float* heat = (lvl == 0) ? h0 : ((lvl == 1) ? h1 : h2);

        int c  = labels[b * NBOX + n];
        int bc = b * C + c;

        float4 bx = reinterpret_cast<const float4*>(boxes)[b * NBOX + n];
        int xi, yi, ri; float invi;
        box_params(bx, W, xi, yi, ri, invi);

        __shared__ int   sx[NBOX], sy[NBOX], sr[NBOX], sjj[NBOX];
        __shared__ float sinv[NBOX];
        __shared__ int   scnt;
        if (tid == 0) {
            int cnt = 0;
            for (int j = 0; j < NBOX; j++) {
                if (j == n) continue;
                if (labels[b * NBOX + j] == c) {
                    float4 bj = reinterpret_cast<const float4*>(boxes)[b * NBOX + j];
                    int xj, yj, rj; float invj;
                    box_params(bj, W, xj, yj, rj, invj);
                    sx[cnt] = xj; sy[cnt] = yj; sr[cnt] = rj;
                    sinv[cnt] = invj; sjj[cnt] = j;
                    cnt++;
                }
            }
            scnt = cnt;
        }
        __syncthreads();
        int cnt = scnt;

        int x0 = max(xi - ri, 0), x1 = min(xi + ri, W - 1);
        int y0 = max(yi - ri, 0), y1 = min(yi + ri, W - 1);
        int nx = x1 - x0 + 1, ny = y1 - y0 + 1;
        int tot = nx * ny;

        float dnl = 0.0f, dpl = 0.0f;
        int dnp = 0;
        const float* hch = heat + (size_t)bc * W * W;

        for (int k = tid; k < tot; k += 256) {
            int px = x0 + (k % nx);
            int py = y0 + (k / nx);
            int dx = px - xi, dy = py - yi;
            float gi = __expf(-(float)(dx * dx + dy * dy) * invi);
            float best = gi;
            int   owner = n;
            for (int q = 0; q < cnt; q++) {
                int ddx = px - sx[q], ddy = py - sy[q];
                if (abs(ddx) <= sr[q] && abs(ddy) <= sr[q]) {
                    float gj = __expf(-(float)(ddx * ddx + ddy * ddy) * sinv[q]);
                    if (gj > best || (gj == best && sjj[q] < owner)) {
                        best = gj; owner = sjj[q];
                    }
                }
            }
            if (owner != n) continue;     // another box owns this pixel

            float h = hch[py * W + px];
            float e = __expf(-h);
            float p = __fdividef(1.0f, 1.0f + e);
            p = fminf(fmaxf(p, 1e-4f), 1.0f - 1e-4f);
            float lb = __logf(1.0f - p) * p * p;  // baseline neg term here

            if (best == 1.0f) {
                dnl -= lb;
                float om = 1.0f - p;
                dpl += __logf(p) * om * om;
                dnp += 1;
            } else {
                float u = 1.0f - best;
                float w = (u * u) * (u * u);
                dnl += lb * (w - 1.0f);
            }
        }

        dnl = warp_sum(dnl);
        dpl = warp_sum(dpl);
        #pragma unroll
        for (int o = 16; o > 0; o >>= 1) dnp += __shfl_xor_sync(0xffffffffu, dnp, o);
        if (lane == 0) { s_red[warp] = dnl; s_red2[warp] = dpl; s_red3[warp] = dnp; }
        __syncthreads();
        if (warp == 0) {
            float a = (lane < 8) ? s_red[lane]  : 0.0f;
            float p2 = (lane < 8) ? s_red2[lane] : 0.0f;
            int   i3 = (lane < 8) ? s_red3[lane] : 0;
            a  = warp_sum(a);
            p2 = warp_sum(p2);
            #pragma unroll
            for (int o = 16; o > 0; o >>= 1) i3 += __shfl_xor_sync(0xffffffffu, i3, o);
            if (lane == 0) {
                if (a  != 0.0f) atomicAdd(&g_nl[bc], a);
                if (p2 != 0.0f) atomicAdd(&g_pl[bc], p2);
                if (i3 != 0)    atomicAdd(&g_np[bc], i3);
            }
        }
    }

    // ---------------- last-block finalize + scratch reset -------------------
    __shared__ unsigned s_last;
    __threadfence();
    __syncthreads();
    if (tid == 0) {
        unsigned v = atomicAdd(&g_done, 1u);
        s_last = (v == TOTAL_BLOCKS - 1) ? 1u : 0u;
    }
    __syncthreads();
    if (s_last) {
        __threadfence();   // acquire all other blocks' atomics
        float acc = 0.0f;
        for (int ch = tid; ch < NCH; ch += 256) {
            float nl = g_nl[ch], pl = g_pl[ch];
            int np = g_np[ch];
            float loss = (np == 0) ? (-nl) : (-(pl + nl) / (float)np);
            acc += fminf(loss, 10.0f);
            g_nl[ch] = 0.0f; g_pl[ch] = 0.0f; g_np[ch] = 0;   // reset for next replay
        }
        acc = warp_sum(acc);
        if (lane == 0) s_red[warp] = acc;
        __syncthreads();
        if (warp == 0) {
            float s = (lane < 8) ? s_red[lane] : 0.0f;
            s = warp_sum(s);
            if (lane == 0) {
                float mean = s / (float)NCH;
                float lm = log1pf(mean);
                out[0] = lm / (1.0f + lm);
                g_done = 0u;                                   // reset counter
            }
        }
    }
}

// ---------------------------------------------------------------------------
extern "C" void kernel_launch(void* const* d_in, const int* in_sizes, int n_in,
                              void* d_out, int out_size) {
    const float* h0     = (const float*)d_in[0];
    const float* h1     = (const float*)d_in[1];
    const float* h2     = (const float*)d_in[2];
    const float* boxes  = (const float*)d_in[3];
    const int*   labels = (const int*)d_in[4];
    (void)in_sizes; (void)n_in; (void)out_size;

    fused_kernel<<<TOTAL_BLOCKS, 256>>>(h0, h1, h2, boxes, labels, (float*)d_out);
}

// round 4
// speedup vs baseline: 1.3674x; 1.2729x over previous
#include <cuda_runtime.h>
#include <cstdint>

// Problem shapes (fixed by the dataset)
#define B     8
#define NBOX  32
#define C     80
#define NCH   (B * C)        // 640

// Block layout: corr first (variable-length tail starts in wave 0), then baseline.
#define NB_CORR (B * NBOX * 3)              // 768
#define NB_L0   1280                        // 2 blocks per lvl0 channel
#define NB_L1   640
#define NB_L2   640
#define TOTAL_BLOCKS (NB_CORR + NB_L0 + NB_L1 + NB_L2)  // 3328

// Scratch (zero at module load; finalizing block restores zeros every call)
__device__ float    g_nl[NCH];
__device__ float    g_pl[NCH];
__device__ int      g_np[NCH];
__device__ unsigned g_done;

// ---------------------------------------------------------------------------
__device__ __forceinline__ float ex2f(float x) {
    float r; asm("ex2.approx.ftz.f32 %0, %1;" : "=f"(r) : "f"(x)); return r;
}
__device__ __forceinline__ float lg2f(float x) {
    float r; asm("lg2.approx.ftz.f32 %0, %1;" : "=f"(r) : "f"(x)); return r;
}

// log(1-p)*p^2 with p = clip(sigmoid(h), 1e-4, 1-1e-4).
// Clip(p) == sigmoid(clamp(h, ±logit(1e-4))), so clamp h instead.
// t = 1+e^{-h}:  log(1-p) = -(h + ln t) = -(h + L*ln2),  p^2 = 2^{-2L}.
__device__ __forceinline__ float neg_term(float h) {
    h = fminf(fmaxf(h, -9.2103404f), 9.2103404f);
    float e = ex2f(h * -1.44269504f);      // e^{-h}
    float t = 1.0f + e;
    float L = lg2f(t);
    float u = fmaf(L, 0.69314718f, h);     // h + ln t  ( = -log(1-p) )
    float it2 = ex2f(L * -2.0f);           // p^2
    return -u * it2;
}

// Box -> (center, radius, 1/(2 sigma^2)) at square level W. __noinline__ so
// the "self" and "conflict" evaluations of the same box are bitwise identical
// (required by the deterministic argmax dedup).
__device__ __noinline__ void box_params(float4 bx, int W,
                                        int& x, int& y, int& r, float& inv2s2) {
    x = (int)floorf(bx.x * (float)W);
    y = (int)floorf(bx.y * (float)W);
    float bw = bx.z * (float)W;
    float bh = bx.w * (float)W;
    int rr = (int)floorf((bw + bh) * 0.25f);
    r = rr < 1 ? 1 : rr;
    float sigma = (float)(2 * r + 1) / 6.0f;
    inv2s2 = 1.0f / (2.0f * sigma * sigma);
}

__device__ __forceinline__ float warp_sum(float v) {
    #pragma unroll
    for (int o = 16; o > 0; o >>= 1) v += __shfl_xor_sync(0xffffffffu, v, o);
    return v;
}

// ---------------------------------------------------------------------------
__global__ __launch_bounds__(256) void fused_kernel(
    const float* __restrict__ h0, const float* __restrict__ h1,
    const float* __restrict__ h2, const float* __restrict__ boxes,
    const int*   __restrict__ labels, float* __restrict__ out)
{
    const int bid = blockIdx.x;
    const int tid = threadIdx.x;
    const int lane = tid & 31, warp = tid >> 5;

    __shared__ float s_red[8], s_red2[8];
    __shared__ int   s_red3[8];

    if (bid >= NB_CORR) {
        // ---------------- baseline: target==0 neg-loss per channel ----------
        int bb = bid - NB_CORR;
        const float* base; int ch, off4, cnt4, chf4;
        if (bb < NB_L0)               { ch = bb >> 1;            base = h0; off4 = (bb & 1) * 2048; cnt4 = 2048; chf4 = 4096; }
        else if (bb < NB_L0 + NB_L1)  { ch = bb - NB_L0;         base = h1; off4 = 0; cnt4 = 1024; chf4 = 1024; }
        else                          { ch = bb - NB_L0 - NB_L1; base = h2; off4 = 0; cnt4 = 256;  chf4 = 256;  }

        const float4* p4 = reinterpret_cast<const float4*>(base) + (size_t)ch * chf4 + off4;
        float acc = 0.0f;
        int i = tid;
        // main: 4 batched independent LDG.128 per iteration (MLP_p1 = 4)
        for (; i + 768 < cnt4; i += 1024) {
            float4 v0 = p4[i];
            float4 v1 = p4[i + 256];
            float4 v2 = p4[i + 512];
            float4 v3 = p4[i + 768];
            acc += neg_term(v0.x); acc += neg_term(v0.y); acc += neg_term(v0.z); acc += neg_term(v0.w);
            acc += neg_term(v1.x); acc += neg_term(v1.y); acc += neg_term(v1.z); acc += neg_term(v1.w);
            acc += neg_term(v2.x); acc += neg_term(v2.y); acc += neg_term(v2.z); acc += neg_term(v2.w);
            acc += neg_term(v3.x); acc += neg_term(v3.y); acc += neg_term(v3.z); acc += neg_term(v3.w);
        }
        for (; i < cnt4; i += 256) {
            float4 v = p4[i];
            acc += neg_term(v.x); acc += neg_term(v.y); acc += neg_term(v.z); acc += neg_term(v.w);
        }
        acc = warp_sum(acc);
        if (lane == 0) s_red[warp] = acc;
        __syncthreads();
        if (warp == 0) {
            float s = (lane < 8) ? s_red[lane] : 0.0f;
            s = warp_sum(s);
            if (lane == 0) atomicAdd(&g_nl[ch], s);
        }
    } else {
        // ---------------- corrections: one block per (box, level) ----------
        int lvl   = bid >> 8;                 // /256
        int boxId = bid & 255;
        int b = boxId >> 5, n = boxId & 31;
        int W = (lvl == 0) ? 128 : ((lvl == 1) ? 64 : 32);
        const float* heat = (lvl == 0) ? h0 : ((lvl == 1) ? h1 : h2);

        int c  = labels[b * NBOX + n];
        int bc = b * C + c;

        float4 bx = reinterpret_cast<const float4*>(boxes)[b * NBOX + n];
        int xi, yi, ri; float invi;
        box_params(bx, W, xi, yi, ri, invi);

        __shared__ int   sx[NBOX], sy[NBOX], sr[NBOX], sjj[NBOX];
        __shared__ float sinv[NBOX];
        __shared__ int   scnt;
        if (tid == 0) {
            int cnt = 0;
            for (int j = 0; j < NBOX; j++) {
                if (j == n) continue;
                if (labels[b * NBOX + j] == c) {
                    float4 bj = reinterpret_cast<const float4*>(boxes)[b * NBOX + j];
                    int xj, yj, rj; float invj;
                    box_params(bj, W, xj, yj, rj, invj);
                    sx[cnt] = xj; sy[cnt] = yj; sr[cnt] = rj;
                    sinv[cnt] = invj; sjj[cnt] = j;
                    cnt++;
                }
            }
            scnt = cnt;
        }
        __syncthreads();
        int cnt = scnt;

        int x0 = max(xi - ri, 0), x1 = min(xi + ri, W - 1);
        int y0 = max(yi - ri, 0), y1 = min(yi + ri, W - 1);
        int nx = x1 - x0 + 1, ny = y1 - y0 + 1;
        int tot = nx * ny;
        float rnx = 1.0f / (float)nx;

        float dnl = 0.0f, dpl = 0.0f;
        int dnp = 0;
        const float* hch = heat + (size_t)bc * W * W;

        for (int k = tid; k < tot; k += 256) {
            // k -> (row, col) without IDIV: float rcp + exact correction
            int row = (int)((float)k * rnx);
            int rem = k - row * nx;
            if (rem < 0)        { row--; rem += nx; }
            else if (rem >= nx) { row++; rem -= nx; }
            int px = x0 + rem;
            int py = y0 + row;

            int dx = px - xi, dy = py - yi;
            float gi = __expf(-(float)(dx * dx + dy * dy) * invi);
            float best = gi;
            int   owner = n;
            for (int q = 0; q < cnt; q++) {
                int ddx = px - sx[q], ddy = py - sy[q];
                if (abs(ddx) <= sr[q] && abs(ddy) <= sr[q]) {
                    float gj = __expf(-(float)(ddx * ddx + ddy * ddy) * sinv[q]);
                    if (gj > best || (gj == best && sjj[q] < owner)) {
                        best = gj; owner = sjj[q];
                    }
                }
            }
            if (owner != n) continue;     // another box owns this pixel

            float h = hch[py * W + px];
            float lb = neg_term(h);       // baseline neg term at this pixel

            if (best == 1.0f) {
                dnl -= lb;
                // pos term: log(p)*(1-p)^2 with p clipped (clip inert for this data)
                float e = __expf(-fminf(fmaxf(h, -9.2103404f), 9.2103404f));
                float t = 1.0f + e;
                float p = __fdividef(1.0f, t);
                float om = 1.0f - p;
                dpl += __logf(p) * om * om;
                dnp += 1;
            } else {
                float u = 1.0f - best;
                float w = (u * u) * (u * u);
                dnl += lb * (w - 1.0f);
            }
        }

        dnl = warp_sum(dnl);
        dpl = warp_sum(dpl);
        #pragma unroll
        for (int o = 16; o > 0; o >>= 1) dnp += __shfl_xor_sync(0xffffffffu, dnp, o);
        if (lane == 0) { s_red[warp] = dnl; s_red2[warp] = dpl; s_red3[warp] = dnp; }
        __syncthreads();
        if (warp == 0) {
            float a  = (lane < 8) ? s_red[lane]  : 0.0f;
            float p2 = (lane < 8) ? s_red2[lane] : 0.0f;
            int   i3 = (lane < 8) ? s_red3[lane] : 0;
            a  = warp_sum(a);
            p2 = warp_sum(p2);
            #pragma unroll
            for (int o = 16; o > 0; o >>= 1) i3 += __shfl_xor_sync(0xffffffffu, i3, o);
            if (lane == 0) {
                if (a  != 0.0f) atomicAdd(&g_nl[bc], a);
                if (p2 != 0.0f) atomicAdd(&g_pl[bc], p2);
                if (i3 != 0)    atomicAdd(&g_np[bc], i3);
            }
        }
    }

    // ---------------- last-block finalize + scratch reset -------------------
    __shared__ unsigned s_last;
    __threadfence();
    __syncthreads();
    if (tid == 0) {
        unsigned v = atomicAdd(&g_done, 1u);
        s_last = (v == TOTAL_BLOCKS - 1) ? 1u : 0u;
    }
    __syncthreads();
    if (s_last) {
        __threadfence();   // acquire all other blocks' atomics
        float acc = 0.0f;
        for (int ch = tid; ch < NCH; ch += 256) {
            float nl = g_nl[ch], pl = g_pl[ch];
            int np = g_np[ch];
            float loss = (np == 0) ? (-nl) : (-(pl + nl) / (float)np);
            acc += fminf(loss, 10.0f);
            g_nl[ch] = 0.0f; g_pl[ch] = 0.0f; g_np[ch] = 0;   // reset for next replay
        }
        acc = warp_sum(acc);
        if (lane == 0) s_red[warp] = acc;
        __syncthreads();
        if (warp == 0) {
            float s = (lane < 8) ? s_red[lane] : 0.0f;
            s = warp_sum(s);
            if (lane == 0) {
                float mean = s / (float)NCH;
                float lm = log1pf(mean);
                out[0] = lm / (1.0f + lm);
                g_done = 0u;                                   // reset counter
            }
        }
    }
}

// ---------------------------------------------------------------------------
extern "C" void kernel_launch(void* const* d_in, const int* in_sizes, int n_in,
                              void* d_out, int out_size) {
    const float* h0     = (const float*)d_in[0];
    const float* h1     = (const float*)d_in[1];
    const float* h2     = (const float*)d_in[2];
    const float* boxes  = (const float*)d_in[3];
    const int*   labels = (const int*)d_in[4];
    (void)in_sizes; (void)n_in; (void)out_size;

    fused_kernel<<<TOTAL_BLOCKS, 256>>>(h0, h1, h2, boxes, labels, (float*)d_out);
}